// round 15
// baseline (speedup 1.0000x reference)
#include <cuda_runtime.h>
#include <cuda_fp16.h>
#include <cstdint>
#include <cstddef>

// ----------------------------------------------------------------------------
// ThickConv2d via Winograd F(2x2,3x3).
// R15: R13 core (CTA 64m x 128n, 8 warps 2x4, warp tile 32x32, rolled ks,
//      strength-reduced addressing) + 4-stage pipeline processing t in PAIRS:
//      the two warps sharing an SMSP (wm=0 / wm=1) traverse each pair in
//      opposite order, de-phasing their LDSM-wait and MMA bursts.
// ----------------------------------------------------------------------------

#define CIN     128
#define NCHAN   8192          // OUT_CH*MID_CH
#define MT      2048          // 8 batches * 16*16 tiles
#define NT_CTA  128           // n per CTA (= 2 output channels)
#define MT_CTA  64            // m-tiles per CTA

#define VSTAGE  (MT_CTA * 256)        // 16384 (64 rows x 256B)
#define USTAGE  (NT_CTA * 256)        // 32768 (128 rows x 256B)
#define STAGE_B (VSTAGE + USTAGE)     // 49152
#define STAGES  4
#define SM_B1   (STAGES * STAGE_B)    // 196608
#define SM_W2   (SM_B1 + 512)
#define SM_B2   (SM_W2 + 512)
#define SM_PART (SM_B2 + 32)
#define SMEM_BYTES (SM_PART + 8 * 128 * 4)   // + part[8][128]  (~201.8 KB)

__device__ __half g_V[(size_t)16 * MT * CIN];      //  8 MB
__device__ __half g_U[(size_t)16 * NCHAN * CIN];   // 32 MB

__device__ __forceinline__ uint32_t smem_u32(const void* p) {
    uint32_t a;
    asm("{ .reg .u64 t; cvta.to.shared.u64 t, %1; cvt.u32.u64 %0, t; }"
        : "=r"(a) : "l"(p));
    return a;
}

__device__ __forceinline__ void cp16(uint32_t s, const void* g) {
    asm volatile("cp.async.cg.shared.global [%0], [%1], 16;"
                 :: "r"(s), "l"(g) : "memory");
}

#define CP_COMMIT() asm volatile("cp.async.commit_group;" ::: "memory")
#define CP_WAIT1()  asm volatile("cp.async.wait_group 1;" ::: "memory")

__device__ __forceinline__ void ldm4(uint32_t* r, uint32_t addr) {
    asm volatile("ldmatrix.sync.aligned.m8n8.x4.shared.b16 {%0,%1,%2,%3}, [%4];"
                 : "=r"(r[0]), "=r"(r[1]), "=r"(r[2]), "=r"(r[3]) : "r"(addr));
}

__device__ __forceinline__ void mma16816(float* c, const uint32_t* a,
                                         const uint32_t* b) {
    asm volatile(
        "mma.sync.aligned.m16n8k16.row.col.f32.f16.f16.f32 "
        "{%0,%1,%2,%3}, {%4,%5,%6,%7}, {%8,%9}, {%0,%1,%2,%3};"
        : "+f"(c[0]), "+f"(c[1]), "+f"(c[2]), "+f"(c[3])
        : "r"(a[0]), "r"(a[1]), "r"(a[2]), "r"(a[3]), "r"(b[0]), "r"(b[1]));
}

// ----------------------------------------------------------------------------
// Transforms (fp32 math, fp16 store).  Blocks [0,1024): input; rest: weight.
// ----------------------------------------------------------------------------
#define IN_BLOCKS (MT * CIN / 256)          // 1024
#define W_BLOCKS  (NCHAN * CIN / 256)       // 4096

__global__ void wino_prep(const float* __restrict__ x,
                          const float* __restrict__ w1) {
    if (blockIdx.x < IN_BLOCKS) {
        int gid = blockIdx.x * 256 + threadIdx.x;     // m*128 + c
        int m = gid >> 7, c = gid & 127;
        int b = m >> 8, ty = (m >> 4) & 15, tx = m & 15;
        const float* xp = x + (((size_t)b * 128 + c) << 10);
        int iy0 = ty * 2 - 1, ix0 = tx * 2 - 1;
        float d[4][4];
        #pragma unroll
        for (int i = 0; i < 4; i++)
            #pragma unroll
            for (int j = 0; j < 4; j++) {
                int iy = iy0 + i, ix = ix0 + j;
                d[i][j] = ((unsigned)iy < 32u && (unsigned)ix < 32u)
                          ? xp[iy * 32 + ix] : 0.0f;
            }
        float tm[4][4], v[4][4];
        #pragma unroll
        for (int j = 0; j < 4; j++) {
            tm[0][j] = d[0][j] - d[2][j];
            tm[1][j] = d[1][j] + d[2][j];
            tm[2][j] = d[2][j] - d[1][j];
            tm[3][j] = d[1][j] - d[3][j];
        }
        #pragma unroll
        for (int i = 0; i < 4; i++) {
            v[i][0] = tm[i][0] - tm[i][2];
            v[i][1] = tm[i][1] + tm[i][2];
            v[i][2] = tm[i][2] - tm[i][1];
            v[i][3] = tm[i][1] - tm[i][3];
        }
        #pragma unroll
        for (int t = 0; t < 16; t++)
            g_V[((size_t)t * MT + m) * CIN + c] = __float2half_rn(v[t >> 2][t & 3]);
        return;
    }
    int gid = (blockIdx.x - IN_BLOCKS) * 256 + threadIdx.x;  // n*128 + c
    int n = gid >> 7, c = gid & 127;
    const float* wp = w1 + ((size_t)n * 128 + c) * 9;
    float g[3][3];
    #pragma unroll
    for (int i = 0; i < 3; i++)
        #pragma unroll
        for (int j = 0; j < 3; j++) g[i][j] = wp[i * 3 + j];
    float gg[4][3], u[4][4];
    #pragma unroll
    for (int j = 0; j < 3; j++) {
        gg[0][j] = g[0][j];
        gg[1][j] = 0.5f * (g[0][j] + g[1][j] + g[2][j]);
        gg[2][j] = 0.5f * (g[0][j] - g[1][j] + g[2][j]);
        gg[3][j] = g[2][j];
    }
    #pragma unroll
    for (int i = 0; i < 4; i++) {
        u[i][0] = gg[i][0];
        u[i][1] = 0.5f * (gg[i][0] + gg[i][1] + gg[i][2]);
        u[i][2] = 0.5f * (gg[i][0] - gg[i][1] + gg[i][2]);
        u[i][3] = gg[i][2];
    }
    #pragma unroll
    for (int t = 0; t < 16; t++)
        g_U[((size_t)t * NCHAN + n) * CIN + c] = __float2half_rn(u[t >> 2][t & 3]);
}

// ----------------------------------------------------------------------------
// Winograd GEMM + inverse transform + fused epilogue.
// 256 threads, 8 warps = 2(m) x 4(n); warp tile 32 m-tiles x 32 n; K=128/t.
// ----------------------------------------------------------------------------
__global__ __launch_bounds__(256, 1)
void wino_gemm(const float* __restrict__ b1, const float* __restrict__ w2,
               const float* __restrict__ b2, float* __restrict__ out) {
    extern __shared__ char smem[];
    const uint32_t sb = smem_u32(smem);
    const int tid = threadIdx.x;
    const int wid = tid >> 5;
    const int lid = tid & 31;
    const int wm  = wid >> 2;          // 0..1  m-half; also the SMSP partner id
    const int wn2 = wid & 3;           // 0..3  n-quarter (32 n each)
    const int ptile = blockIdx.x & 31;     // 32 m-tile groups (64 each)
    const int ntile = blockIdx.x >> 5;     // 64 n groups (2 channels each)

    float* b1s  = (float*)(smem + SM_B1);
    float* w2f  = (float*)(smem + SM_W2);
    float* b2f  = (float*)(smem + SM_B2);
    float* part = (float*)(smem + SM_PART);   // [8 warps][128]

    if (tid < 128) {
        b1s[tid] = b1[ntile * 128 + tid];
        w2f[tid] = w2[ntile * 128 + tid];
    }
    if (tid < 2) b2f[tid] = b2[ntile * 2 + tid];

    const int r5 = tid >> 4, u5 = tid & 15;   // loader: (row, 16B-chunk)

    auto load_stage = [&](int t) {
        const uint32_t sV = sb + (t & 3) * STAGE_B;
        const uint32_t sU = sV + VSTAGE;
        const __half* Vg = g_V + ((size_t)t * MT + ptile * MT_CTA) * CIN;
        const __half* Ug = g_U + ((size_t)t * NCHAN + ntile * NT_CTA) * CIN;
        #pragma unroll
        for (int i = 0; i < 4; i++) {          // V: 64 rows x 16 chunks
            int r = r5 + i * 16;
            cp16(sV + r * 256 + ((u5 ^ (r & 7)) << 4),
                 Vg + (size_t)r * CIN + u5 * 8);
        }
        #pragma unroll
        for (int i = 0; i < 8; i++) {          // U: 128 rows x 16 chunks
            int r = r5 + i * 16;
            cp16(sU + r * 256 + ((u5 ^ (r & 7)) << 4),
                 Ug + (size_t)r * CIN + u5 * 8);
        }
    };

    // preload pairs 0 and 1 (one commit group per pair)
    load_stage(0); load_stage(1); CP_COMMIT();
    load_stage(2); load_stage(3); CP_COMMIT();

    float acc[2][2][2][4][4];   // [p][q][mf][nf][e]
    #pragma unroll
    for (int p = 0; p < 2; p++)
        #pragma unroll
        for (int q = 0; q < 2; q++)
            #pragma unroll
            for (int mf = 0; mf < 2; mf++)
                #pragma unroll
                for (int nf = 0; nf < 4; nf++)
                    #pragma unroll
                    for (int e = 0; e < 4; e++) acc[p][q][mf][nf][e] = 0.0f;

    // strength-reduced ldmatrix addressing: addr = C + ((ks ^ rr) << 5)
    const int raBit = lid >> 4;
    const int rbBit = (lid >> 3) & 1;
    uint32_t aC[2], bC[2];
    uint32_t aRR[2], bRR[2];
    #pragma unroll
    for (int mf = 0; mf < 2; mf++) {
        int ra = wm * 32 + mf * 16 + (lid & 15);
        aC[mf]  = ra * 256 + ((raBit ^ (ra & 1)) << 4);
        aRR[mf] = (ra >> 1) & 3;
    }
    #pragma unroll
    for (int nf2 = 0; nf2 < 2; nf2++) {
        int rb = wn2 * 32 + nf2 * 16 + (lid & 7) + ((lid >> 4) << 3);
        bC[nf2]  = rb * 256 + ((rbBit ^ (rb & 1)) << 4);
        bRR[nf2] = (rb >> 1) & 3;
    }

    constexpr int ATc[2][4] = {{1, 1, 1, 0}, {0, 1, -1, -1}};

    // compute one t: rolled ks GEMM + inverse-transform fold
    auto compute_t = [&](int t) {
        const uint32_t vBase = sb + (t & 3) * STAGE_B;
        const uint32_t uBase = vBase + VSTAGE;
        const uint32_t aB0 = vBase + aC[0], aB1 = vBase + aC[1];
        const uint32_t bB0 = uBase + bC[0], bB1 = uBase + bC[1];

        float prod[2][4][4] = {};
        #pragma unroll 1
        for (int ks = 0; ks < 8; ks++) {
            uint32_t a[2][4];
            ldm4(a[0], aB0 + (uint32_t)((ks ^ aRR[0]) << 5));
            ldm4(a[1], aB1 + (uint32_t)((ks ^ aRR[1]) << 5));
            uint32_t b[4][2];
            {
                uint32_t tt[4];
                ldm4(tt, bB0 + (uint32_t)((ks ^ bRR[0]) << 5));
                b[0][0] = tt[0]; b[0][1] = tt[1];
                b[1][0] = tt[2]; b[1][1] = tt[3];
                ldm4(tt, bB1 + (uint32_t)((ks ^ bRR[1]) << 5));
                b[2][0] = tt[0]; b[2][1] = tt[1];
                b[3][0] = tt[2]; b[3][1] = tt[3];
            }
            #pragma unroll
            for (int mf = 0; mf < 2; mf++)
                #pragma unroll
                for (int nf = 0; nf < 4; nf++)
                    mma16816(prod[mf][nf], a[mf], b[nf]);
        }

        const int ti = t >> 2, tj = t & 3;
        #pragma unroll
        for (int p = 0; p < 2; p++) {
            if (ATc[p][ti] == 0) continue;
            #pragma unroll
            for (int q = 0; q < 2; q++) {
                if (ATc[q][tj] == 0) continue;
                const float s = (float)(ATc[p][ti] * ATc[q][tj]);
                #pragma unroll
                for (int mf = 0; mf < 2; mf++)
                    #pragma unroll
                    for (int nf = 0; nf < 4; nf++)
                        #pragma unroll
                        for (int e = 0; e < 4; e++)
                            acc[p][q][mf][nf][e] += s * prod[mf][nf][e];
            }
        }
    };

    // pair loop: SMSP partners (wm=0 vs wm=1) traverse each pair in
    // opposite order, de-phasing LDSM waits vs MMA bursts.
    #pragma unroll 1
    for (int pp = 0; pp < 8; pp++) {
        CP_WAIT1();               // pair pp resident (<=1 group pending)
        __syncthreads();          // pair visible; all warps past pair pp-1
        const int t0 = 2 * pp;
        if (wm == 0) { compute_t(t0);     compute_t(t0 + 1); }
        else         { compute_t(t0 + 1); compute_t(t0);     }
        __syncthreads();          // all warps done with pair pp's slots
        if (pp + 2 < 8) { load_stage(t0 + 4); load_stage(t0 + 5); }
        CP_COMMIT();
    }

    // ---------------- epilogue ----------------
    // value (mf,nf,e): local m-row = mf*16 + (lid>>2) + 8*(e>>1)  (0..31)
    //                  nt = wn2*32 + nf*8 + 2*(lid&3) + (e&1)     (0..127)
    #pragma unroll
    for (int p = 0; p < 2; p++) {
        #pragma unroll
        for (int q = 0; q < 2; q++) {
            #pragma unroll
            for (int mf = 0; mf < 2; mf++) {
                #pragma unroll
                for (int rh = 0; rh < 2; rh++) {
                    float s = 0.0f;
                    #pragma unroll
                    for (int nf = 0; nf < 4; nf++) {
                        #pragma unroll
                        for (int cc = 0; cc < 2; cc++) {
                            int nt = wn2 * 32 + nf * 8 + (lid & 3) * 2 + cc;
                            float v = acc[p][q][mf][nf][rh * 2 + cc] + b1s[nt];
                            v = (v < 0.0f) ? 0.1f * v : v;
                            s = fmaf(w2f[nt], v, s);
                        }
                    }
                    s += __shfl_xor_sync(0xFFFFFFFFu, s, 1);
                    s += __shfl_xor_sync(0xFFFFFFFFu, s, 2);
                    if ((lid & 3) == 0) {
                        int row = mf * 16 + rh * 8 + (lid >> 2);
                        part[wid * 128 + (p * 2 + q) * 32 + row] = s;
                    }
                }
            }
        }
    }
    __syncthreads();

    // combine the two n-warps per channel; write 512 outputs (2 per thread)
    #pragma unroll
    for (int io = 0; io < 2; io++) {
        int v      = io * 256 + tid;       // 0..511
        int chan   = v >> 8;               // 0..1
        int rem    = v & 255;
        int mrow64 = rem >> 2;             // 0..63
        int pos    = rem & 3;              // p*2+q
        int wmg    = mrow64 >> 5;
        int row32  = mrow64 & 31;
        float s = part[(wmg * 4 + 2 * chan) * 128 + pos * 32 + row32]
                + part[(wmg * 4 + 2 * chan + 1) * 128 + pos * 32 + row32]
                + b2f[chan];
        int m = ptile * MT_CTA + mrow64;
        int b = m >> 8, ty = (m >> 4) & 15, tx = m & 15;
        int p = pos >> 1, q = pos & 1;
        int o = ntile * 2 + chan;
        out[(((size_t)b * 128 + o) * 32 + 2 * ty + p) * 32 + 2 * tx + q] = s;
    }
}

// ----------------------------------------------------------------------------
extern "C" void kernel_launch(void* const* d_in, const int* in_sizes, int n_in,
                              void* d_out, int out_size) {
    const float* x  = (const float*)d_in[0];
    const float* w1 = (const float*)d_in[1];
    const float* b1 = (const float*)d_in[2];
    const float* w2 = (const float*)d_in[3];
    const float* b2 = (const float*)d_in[4];
    float* out = (float*)d_out;

    cudaFuncSetAttribute(wino_gemm, cudaFuncAttributeMaxDynamicSharedMemorySize,
                         SMEM_BYTES);

    wino_prep<<<IN_BLOCKS + W_BLOCKS, 256>>>(x, w1);
    wino_gemm<<<32 * 64, 256, SMEM_BYTES>>>(b1, w2, b2, out);
}

// round 16
// speedup vs baseline: 1.1730x; 1.1730x over previous
#include <cuda_runtime.h>
#include <cuda_fp16.h>
#include <cstdint>
#include <cstddef>

// ----------------------------------------------------------------------------
// ThickConv2d via Winograd F(2x2,3x3).
// R16: 2 independent CTAs per SM (R6 lesson: de-phased CTAs fill each other's
//      LDSM-stall windows). CTA 64m x 64n, 128 thr (4 warps 2x2), warp tile
//      32x32, rolled ks + strength-reduced addressing, 3-stage cp.async.
// ----------------------------------------------------------------------------

#define CIN     128
#define NCHAN   8192          // OUT_CH*MID_CH
#define MT      2048          // 8 batches * 16*16 tiles
#define NT_CTA  64            // n per CTA (= 1 output channel)
#define MT_CTA  64            // m-tiles per CTA

#define VSTAGE  (MT_CTA * 256)        // 16384 (64 rows x 256B)
#define USTAGE  (NT_CTA * 256)        // 16384 (64 rows x 256B)
#define STAGE_B (VSTAGE + USTAGE)     // 32768
#define STAGES  3
#define SM_B1   (STAGES * STAGE_B)    // 98304
#define SM_W2   (SM_B1 + 256)
#define SM_B2   (SM_W2 + 256)
#define SM_PART (SM_B2 + 16)
#define SMEM_BYTES (SM_PART + 4 * 128 * 4)   // ~100.9 KB per CTA

__device__ __half g_V[(size_t)16 * MT * CIN];      //  8 MB
__device__ __half g_U[(size_t)16 * NCHAN * CIN];   // 32 MB

__device__ __forceinline__ uint32_t smem_u32(const void* p) {
    uint32_t a;
    asm("{ .reg .u64 t; cvta.to.shared.u64 t, %1; cvt.u32.u64 %0, t; }"
        : "=r"(a) : "l"(p));
    return a;
}

__device__ __forceinline__ void cp16(uint32_t s, const void* g) {
    asm volatile("cp.async.cg.shared.global [%0], [%1], 16;"
                 :: "r"(s), "l"(g) : "memory");
}

#define CP_COMMIT() asm volatile("cp.async.commit_group;" ::: "memory")
#define CP_WAIT1()  asm volatile("cp.async.wait_group 1;" ::: "memory")

__device__ __forceinline__ void ldm4(uint32_t* r, uint32_t addr) {
    asm volatile("ldmatrix.sync.aligned.m8n8.x4.shared.b16 {%0,%1,%2,%3}, [%4];"
                 : "=r"(r[0]), "=r"(r[1]), "=r"(r[2]), "=r"(r[3]) : "r"(addr));
}

__device__ __forceinline__ void mma16816(float* c, const uint32_t* a,
                                         const uint32_t* b) {
    asm volatile(
        "mma.sync.aligned.m16n8k16.row.col.f32.f16.f16.f32 "
        "{%0,%1,%2,%3}, {%4,%5,%6,%7}, {%8,%9}, {%0,%1,%2,%3};"
        : "+f"(c[0]), "+f"(c[1]), "+f"(c[2]), "+f"(c[3])
        : "r"(a[0]), "r"(a[1]), "r"(a[2]), "r"(a[3]), "r"(b[0]), "r"(b[1]));
}

// ----------------------------------------------------------------------------
// Transforms (fp32 math, fp16 store).  Blocks [0,1024): input; rest: weight.
// ----------------------------------------------------------------------------
#define IN_BLOCKS (MT * CIN / 256)          // 1024
#define W_BLOCKS  (NCHAN * CIN / 256)       // 4096

__global__ void wino_prep(const float* __restrict__ x,
                          const float* __restrict__ w1) {
    if (blockIdx.x < IN_BLOCKS) {
        int gid = blockIdx.x * 256 + threadIdx.x;     // m*128 + c
        int m = gid >> 7, c = gid & 127;
        int b = m >> 8, ty = (m >> 4) & 15, tx = m & 15;
        const float* xp = x + (((size_t)b * 128 + c) << 10);
        int iy0 = ty * 2 - 1, ix0 = tx * 2 - 1;
        float d[4][4];
        #pragma unroll
        for (int i = 0; i < 4; i++)
            #pragma unroll
            for (int j = 0; j < 4; j++) {
                int iy = iy0 + i, ix = ix0 + j;
                d[i][j] = ((unsigned)iy < 32u && (unsigned)ix < 32u)
                          ? xp[iy * 32 + ix] : 0.0f;
            }
        float tm[4][4], v[4][4];
        #pragma unroll
        for (int j = 0; j < 4; j++) {
            tm[0][j] = d[0][j] - d[2][j];
            tm[1][j] = d[1][j] + d[2][j];
            tm[2][j] = d[2][j] - d[1][j];
            tm[3][j] = d[1][j] - d[3][j];
        }
        #pragma unroll
        for (int i = 0; i < 4; i++) {
            v[i][0] = tm[i][0] - tm[i][2];
            v[i][1] = tm[i][1] + tm[i][2];
            v[i][2] = tm[i][2] - tm[i][1];
            v[i][3] = tm[i][1] - tm[i][3];
        }
        #pragma unroll
        for (int t = 0; t < 16; t++)
            g_V[((size_t)t * MT + m) * CIN + c] = __float2half_rn(v[t >> 2][t & 3]);
        return;
    }
    int gid = (blockIdx.x - IN_BLOCKS) * 256 + threadIdx.x;  // n*128 + c
    int n = gid >> 7, c = gid & 127;
    const float* wp = w1 + ((size_t)n * 128 + c) * 9;
    float g[3][3];
    #pragma unroll
    for (int i = 0; i < 3; i++)
        #pragma unroll
        for (int j = 0; j < 3; j++) g[i][j] = wp[i * 3 + j];
    float gg[4][3], u[4][4];
    #pragma unroll
    for (int j = 0; j < 3; j++) {
        gg[0][j] = g[0][j];
        gg[1][j] = 0.5f * (g[0][j] + g[1][j] + g[2][j]);
        gg[2][j] = 0.5f * (g[0][j] - g[1][j] + g[2][j]);
        gg[3][j] = g[2][j];
    }
    #pragma unroll
    for (int i = 0; i < 4; i++) {
        u[i][0] = gg[i][0];
        u[i][1] = 0.5f * (gg[i][0] + gg[i][1] + gg[i][2]);
        u[i][2] = 0.5f * (gg[i][0] - gg[i][1] + gg[i][2]);
        u[i][3] = gg[i][2];
    }
    #pragma unroll
    for (int t = 0; t < 16; t++)
        g_U[((size_t)t * NCHAN + n) * CIN + c] = __float2half_rn(u[t >> 2][t & 3]);
}

// ----------------------------------------------------------------------------
// Winograd GEMM + inverse transform + fused epilogue.
// 128 threads, 4 warps = 2(m) x 2(n); warp tile 32 m-tiles x 32 n; K=128/t.
// 2 CTAs/SM -> each SMSP hosts one warp from each CTA, independently phased.
// ----------------------------------------------------------------------------
__global__ __launch_bounds__(128, 2)
void wino_gemm(const float* __restrict__ b1, const float* __restrict__ w2,
               const float* __restrict__ b2, float* __restrict__ out) {
    extern __shared__ char smem[];
    const uint32_t sb = smem_u32(smem);
    const int tid = threadIdx.x;
    const int wid = tid >> 5;
    const int lid = tid & 31;
    const int wm  = wid >> 1;          // 0..1  m-half (32 m-tiles each)
    const int wn  = wid & 1;           // 0..1  n-half (32 n each)
    const int ptile = blockIdx.x & 31;     // 32 m-tile groups (64 each)
    const int ntile = blockIdx.x >> 5;     // 128 channels

    float* b1s  = (float*)(smem + SM_B1);
    float* w2f  = (float*)(smem + SM_W2);
    float* b2f  = (float*)(smem + SM_B2);
    float* part = (float*)(smem + SM_PART);   // [4 warps][128]

    if (tid < 64) {
        b1s[tid] = b1[ntile * 64 + tid];
        w2f[tid] = w2[ntile * 64 + tid];
    }
    if (tid == 0) b2f[0] = b2[ntile];

    const int r5 = tid >> 4, u5 = tid & 15;   // loader: (row, 16B-chunk)

    auto load_stage = [&](int t) {
        const uint32_t sV = sb + (t % STAGES) * STAGE_B;
        const uint32_t sU = sV + VSTAGE;
        const __half* Vg = g_V + ((size_t)t * MT + ptile * MT_CTA) * CIN;
        const __half* Ug = g_U + ((size_t)t * NCHAN + ntile * NT_CTA) * CIN;
        #pragma unroll
        for (int i = 0; i < 8; i++) {          // V: 64 rows x 16 chunks
            int r = r5 + i * 8;
            cp16(sV + r * 256 + ((u5 ^ (r & 7)) << 4),
                 Vg + (size_t)r * CIN + u5 * 8);
        }
        #pragma unroll
        for (int i = 0; i < 8; i++) {          // U: 64 rows x 16 chunks
            int r = r5 + i * 8;
            cp16(sU + r * 256 + ((u5 ^ (r & 7)) << 4),
                 Ug + (size_t)r * CIN + u5 * 8);
        }
    };

    load_stage(0); CP_COMMIT();
    load_stage(1); CP_COMMIT();

    float acc[2][2][2][4][4];   // [p][q][mf][nf][e]
    #pragma unroll
    for (int p = 0; p < 2; p++)
        #pragma unroll
        for (int q = 0; q < 2; q++)
            #pragma unroll
            for (int mf = 0; mf < 2; mf++)
                #pragma unroll
                for (int nf = 0; nf < 4; nf++)
                    #pragma unroll
                    for (int e = 0; e < 4; e++) acc[p][q][mf][nf][e] = 0.0f;

    // strength-reduced ldmatrix addressing: addr = C + ((ks ^ rr) << 5)
    const int raBit = lid >> 4;
    const int rbBit = (lid >> 3) & 1;
    uint32_t aC[2], bC[2];
    uint32_t aRR[2], bRR[2];
    #pragma unroll
    for (int mf = 0; mf < 2; mf++) {
        int ra = wm * 32 + mf * 16 + (lid & 15);
        aC[mf]  = ra * 256 + ((raBit ^ (ra & 1)) << 4);
        aRR[mf] = (ra >> 1) & 3;
    }
    #pragma unroll
    for (int nf2 = 0; nf2 < 2; nf2++) {
        int rb = wn * 32 + nf2 * 16 + (lid & 7) + ((lid >> 4) << 3);
        bC[nf2]  = rb * 256 + ((rbBit ^ (rb & 1)) << 4);
        bRR[nf2] = (rb >> 1) & 3;
    }

    constexpr int ATc[2][4] = {{1, 1, 1, 0}, {0, 1, -1, -1}};

    #pragma unroll
    for (int t = 0; t < 16; t++) {
        CP_WAIT1();               // stage for t resident (<=1 group pending)
        __syncthreads();          // all warps done with stage (t+2)%3
        if (t + 2 < 16) load_stage(t + 2);
        CP_COMMIT();

        const uint32_t vBase = sb + (t % STAGES) * STAGE_B;
        const uint32_t uBase = vBase + VSTAGE;
        const uint32_t aB0 = vBase + aC[0], aB1 = vBase + aC[1];
        const uint32_t bB0 = uBase + bC[0], bB1 = uBase + bC[1];

        float prod[2][4][4] = {};
        #pragma unroll 1
        for (int ks = 0; ks < 8; ks++) {
            uint32_t a[2][4];
            ldm4(a[0], aB0 + (uint32_t)((ks ^ aRR[0]) << 5));
            ldm4(a[1], aB1 + (uint32_t)((ks ^ aRR[1]) << 5));
            uint32_t b[4][2];
            {
                uint32_t tt[4];
                ldm4(tt, bB0 + (uint32_t)((ks ^ bRR[0]) << 5));
                b[0][0] = tt[0]; b[0][1] = tt[1];
                b[1][0] = tt[2]; b[1][1] = tt[3];
                ldm4(tt, bB1 + (uint32_t)((ks ^ bRR[1]) << 5));
                b[2][0] = tt[0]; b[2][1] = tt[1];
                b[3][0] = tt[2]; b[3][1] = tt[3];
            }
            #pragma unroll
            for (int mf = 0; mf < 2; mf++)
                #pragma unroll
                for (int nf = 0; nf < 4; nf++)
                    mma16816(prod[mf][nf], a[mf], b[nf]);
        }

        // inverse-transform accumulate (A entries 0/+-1 -> pure add/sub)
        const int ti = t >> 2, tj = t & 3;
        #pragma unroll
        for (int p = 0; p < 2; p++) {
            if (ATc[p][ti] == 0) continue;
            #pragma unroll
            for (int q = 0; q < 2; q++) {
                if (ATc[q][tj] == 0) continue;
                const float s = (float)(ATc[p][ti] * ATc[q][tj]);
                #pragma unroll
                for (int mf = 0; mf < 2; mf++)
                    #pragma unroll
                    for (int nf = 0; nf < 4; nf++)
                        #pragma unroll
                        for (int e = 0; e < 4; e++)
                            acc[p][q][mf][nf][e] += s * prod[mf][nf][e];
            }
        }
    }

    // ---------------- epilogue ----------------
    // value (mf,nf,e): local m-row = mf*16 + (lid>>2) + 8*(e>>1)  (0..31)
    //                  nt = wn*32 + nf*8 + 2*(lid&3) + (e&1)      (0..63)
    #pragma unroll
    for (int p = 0; p < 2; p++) {
        #pragma unroll
        for (int q = 0; q < 2; q++) {
            #pragma unroll
            for (int mf = 0; mf < 2; mf++) {
                #pragma unroll
                for (int rh = 0; rh < 2; rh++) {
                    float s = 0.0f;
                    #pragma unroll
                    for (int nf = 0; nf < 4; nf++) {
                        #pragma unroll
                        for (int cc = 0; cc < 2; cc++) {
                            int nt = wn * 32 + nf * 8 + (lid & 3) * 2 + cc;
                            float v = acc[p][q][mf][nf][rh * 2 + cc] + b1s[nt];
                            v = (v < 0.0f) ? 0.1f * v : v;
                            s = fmaf(w2f[nt], v, s);
                        }
                    }
                    s += __shfl_xor_sync(0xFFFFFFFFu, s, 1);
                    s += __shfl_xor_sync(0xFFFFFFFFu, s, 2);
                    if ((lid & 3) == 0) {
                        int row = mf * 16 + rh * 8 + (lid >> 2);
                        part[wid * 128 + (p * 2 + q) * 32 + row] = s;
                    }
                }
            }
        }
    }
    __syncthreads();

    // combine the two n-warps; write 256 outputs (2 per thread)
    #pragma unroll
    for (int io = 0; io < 2; io++) {
        int v      = io * 128 + tid;       // 0..255
        int mrow64 = v >> 2;               // 0..63
        int pos    = v & 3;                // p*2+q
        int wmg    = mrow64 >> 5;
        int row32  = mrow64 & 31;
        float s = part[(wmg * 2 + 0) * 128 + pos * 32 + row32]
                + part[(wmg * 2 + 1) * 128 + pos * 32 + row32]
                + b2f[0];
        int m = ptile * MT_CTA + mrow64;
        int b = m >> 8, ty = (m >> 4) & 15, tx = m & 15;
        int p = pos >> 1, q = pos & 1;
        out[(((size_t)b * 128 + ntile) * 32 + 2 * ty + p) * 32 + 2 * tx + q] = s;
    }
}

// ----------------------------------------------------------------------------
extern "C" void kernel_launch(void* const* d_in, const int* in_sizes, int n_in,
                              void* d_out, int out_size) {
    const float* x  = (const float*)d_in[0];
    const float* w1 = (const float*)d_in[1];
    const float* b1 = (const float*)d_in[2];
    const float* w2 = (const float*)d_in[3];
    const float* b2 = (const float*)d_in[4];
    float* out = (float*)d_out;

    cudaFuncSetAttribute(wino_gemm, cudaFuncAttributeMaxDynamicSharedMemorySize,
                         SMEM_BYTES);

    wino_prep<<<IN_BLOCKS + W_BLOCKS, 256>>>(x, w1);
    wino_gemm<<<32 * 128, 128, SMEM_BYTES>>>(b1, w2, b2, out);
}